// round 5
// baseline (speedup 1.0000x reference)
#include <cuda_runtime.h>
#include <cuda_bf16.h>
#include <math.h>

#define N_NODES 100000
#define N_EDGES 1000000

// Scratch (device globals — no dynamic allocation allowed)
__device__ __align__(16) float g_dinv[N_NODES];               // deg -> dinv (in place)
__device__ __align__(16) float g_xw[(size_t)N_NODES * 128];   // [:,0:64]=user xw, [:,64:128]=movie xw
__device__ __align__(16) float g_agg[(size_t)N_NODES * 128];  // aggregated output of both convs

// ---------------------------------------------------------------------------
// K0: init degree with self-loop weight 1
__global__ void k_deg_init() {
    int i = blockIdx.x * blockDim.x + threadIdx.x;
    if (i < N_NODES) g_dinv[i] = 1.0f;
}

// K1: accumulate edge weights into degree at col  (edge_index is int32!)
__global__ void k_deg_accum(const int* __restrict__ ei, const float* __restrict__ ew) {
    int e = blockIdx.x * blockDim.x + threadIdx.x;
    if (e < N_EDGES) {
        int col = ei[N_EDGES + e];
        atomicAdd(&g_dinv[col], ew[e]);
    }
}

// K2: deg -> rsqrt(deg)
__global__ void k_dinv() {
    int i = blockIdx.x * blockDim.x + threadIdx.x;
    if (i < N_NODES) {
        float d = g_dinv[i];
        g_dinv[i] = (d > 0.0f) ? rsqrtf(d) : 0.0f;
    }
}

// K3: xw = x@W (both convs), and init agg with self-loop term + bias:
//     agg[n,j] = dinv[n]^2 * xw[n,j] + b[j]
__global__ void __launch_bounds__(128) k_xw(
    const float* __restrict__ user_x, const float* __restrict__ movie_x,
    const float* __restrict__ Wu, const float* __restrict__ bu,
    const float* __restrict__ Wm, const float* __restrict__ bm)
{
    int n = blockIdx.x;
    int j = threadIdx.x;  // 0..127
    __shared__ float xs[21];
    if (j < 3)       xs[j] = user_x[(size_t)n * 3 + j];
    else if (j < 21) xs[j] = movie_x[(size_t)n * 18 + (j - 3)];
    __syncthreads();

    float acc = 0.0f, bias;
    if (j < 64) {
        #pragma unroll
        for (int k = 0; k < 3; k++) acc += xs[k] * Wu[k * 64 + j];
        bias = bu[j];
    } else {
        int jj = j - 64;
        #pragma unroll
        for (int k = 0; k < 18; k++) acc += xs[3 + k] * Wm[k * 64 + jj];
        bias = bm[jj];
    }
    float dv = g_dinv[n];
    size_t o = (size_t)n * 128 + j;
    g_xw[o]  = acc;
    g_agg[o] = dv * dv * acc + bias;
}

// K4: scatter-aggregate. One warp per edge; each lane handles 4 columns via
// float4 gather + vector reduction (red.global.add.v4.f32, sm_90+).
__global__ void __launch_bounds__(256) k_scatter(
    const int* __restrict__ ei, const float* __restrict__ ew)
{
    int gw = (blockIdx.x * blockDim.x + threadIdx.x) >> 5;  // global warp = edge id
    int lane = threadIdx.x & 31;
    if (gw >= N_EDGES) return;

    int row = ei[gw];
    int col = ei[N_EDGES + gw];
    float norm = g_dinv[row] * ew[gw] * g_dinv[col];

    const float4* src = reinterpret_cast<const float4*>(g_xw + (size_t)row * 128) + lane;
    float4 v = *src;
    v.x *= norm; v.y *= norm; v.z *= norm; v.w *= norm;

    float* dst = g_agg + (size_t)col * 128 + lane * 4;
    asm volatile("red.global.add.v4.f32 [%0], {%1, %2, %3, %4};"
                 :: "l"(dst), "f"(v.x), "f"(v.y), "f"(v.z), "f"(v.w)
                 : "memory");
}

// K5: MLP head. Block = 128 threads (thread j = hidden channel j), 4 nodes per
// iteration so each W1 element loaded once serves 4 FMAs.
__global__ void __launch_bounds__(128) k_mlp(
    const float* __restrict__ W1, const float* __restrict__ b1,
    const float* __restrict__ W2, const float* __restrict__ b2,
    float* __restrict__ out)
{
    __shared__ float v[4][128];
    __shared__ float hsum[4][4];
    int j = threadIdx.x;
    int warp = j >> 5, lane = j & 31;
    float w2j = W2[j];
    float b1j = b1[j];
    float b2v = b2[0];

    for (int n0 = blockIdx.x * 4; n0 < N_NODES; n0 += gridDim.x * 4) {
        #pragma unroll
        for (int nd = 0; nd < 4; nd++)
            v[nd][j] = g_agg[(size_t)(n0 + nd) * 128 + j];
        __syncthreads();

        float a0 = b1j, a1 = b1j, a2 = b1j, a3 = b1j;
        #pragma unroll 8
        for (int k = 0; k < 128; k++) {
            float w = W1[k * 128 + j];
            a0 = fmaf(v[0][k], w, a0);
            a1 = fmaf(v[1][k], w, a1);
            a2 = fmaf(v[2][k], w, a2);
            a3 = fmaf(v[3][k], w, a3);
        }
        float p0 = fmaxf(a0, 0.0f) * w2j;
        float p1 = fmaxf(a1, 0.0f) * w2j;
        float p2 = fmaxf(a2, 0.0f) * w2j;
        float p3 = fmaxf(a3, 0.0f) * w2j;
        #pragma unroll
        for (int off = 16; off > 0; off >>= 1) {
            p0 += __shfl_xor_sync(0xFFFFFFFFu, p0, off);
            p1 += __shfl_xor_sync(0xFFFFFFFFu, p1, off);
            p2 += __shfl_xor_sync(0xFFFFFFFFu, p2, off);
            p3 += __shfl_xor_sync(0xFFFFFFFFu, p3, off);
        }
        if (lane == 0) {
            hsum[0][warp] = p0; hsum[1][warp] = p1;
            hsum[2][warp] = p2; hsum[3][warp] = p3;
        }
        __syncthreads();
        if (j < 4) {
            out[n0 + j] = hsum[j][0] + hsum[j][1] + hsum[j][2] + hsum[j][3] + b2v;
        }
        __syncthreads();
    }
}

// ---------------------------------------------------------------------------
extern "C" void kernel_launch(void* const* d_in, const int* in_sizes, int n_in,
                              void* d_out, int out_size) {
    const float* user_x  = (const float*)d_in[0];
    const float* movie_x = (const float*)d_in[1];
    const int*   ei      = (const int*)d_in[2];   // int32 (JAX x64 disabled)
    const float* ea      = (const float*)d_in[3];
    const float* W_user  = (const float*)d_in[4];
    const float* b_user  = (const float*)d_in[5];
    const float* W_movie = (const float*)d_in[6];
    const float* b_movie = (const float*)d_in[7];
    const float* W1      = (const float*)d_in[8];
    const float* b1      = (const float*)d_in[9];
    const float* W2      = (const float*)d_in[10];
    const float* b2      = (const float*)d_in[11];
    float* out = (float*)d_out;

    k_deg_init<<<(N_NODES + 255) / 256, 256>>>();
    k_deg_accum<<<(N_EDGES + 255) / 256, 256>>>(ei, ea);
    k_dinv<<<(N_NODES + 255) / 256, 256>>>();
    k_xw<<<N_NODES, 128>>>(user_x, movie_x, W_user, b_user, W_movie, b_movie);
    k_scatter<<<N_EDGES / 8, 256>>>(ei, ea);
    k_mlp<<<N_NODES / 4, 128>>>(W1, b1, W2, b2, out);
}